// round 2
// baseline (speedup 1.0000x reference)
#include <cuda_runtime.h>
#include <math_constants.h>

// Problem constants (fixed shapes from reference)
#define KB 32          // batch
#define KT 8192        // time
#define KC 256         // channels
#define KW 21          // windows: 1 + 4 + 16
#define TILE 32        // rows staged per CTA
#define NQ  64         // float4 quads per row (KC/4)
#define NTHREADS 64

__device__ __forceinline__ void atomic_max_f32(float* addr, float v) {
    // Order-isomorphic int trick; correct for all non-NaN floats.
    if (v >= 0.0f) {
        atomicMax(reinterpret_cast<int*>(addr), __float_as_int(v));
    } else {
        atomicMin(reinterpret_cast<unsigned int*>(addr), __float_as_uint(v));
    }
}

__global__ void spp_init_kernel(float* __restrict__ out, int n) {
    int i = blockIdx.x * blockDim.x + threadIdx.x;
    if (i < n) out[i] = -CUDART_INF_F;
}

__device__ __forceinline__ float4 f4max(float4 a, float4 b) {
    a.x = fmaxf(a.x, b.x);
    a.y = fmaxf(a.y, b.y);
    a.z = fmaxf(a.z, b.z);
    a.w = fmaxf(a.w, b.w);
    return a;
}

__global__ __launch_bounds__(NTHREADS) void spp_kernel(
    const float4* __restrict__ seq,     // [B, T, C] as float4: [B, T, NQ]
    const int* __restrict__ lengths,    // [B]
    float* __restrict__ out)            // [B, W, C]
{
    __shared__ float4 sm[TILE * NQ];    // 32 KB

    const int b  = blockIdx.y;
    const int L  = lengths[b];
    const int t0 = blockIdx.x * TILE;
    if (t0 >= L) return;

    const int nrows = min(TILE, L - t0);
    const int t1    = t0 + nrows;
    const int tid   = threadIdx.x;

    // ---- Stage tile into SMEM, computing per-thread column max on the fly.
    // i = tid + k*64  =>  quad(i) == tid always, row(i) == k.
    // Each iteration: 64 threads load one contiguous 1 KB row (LDG.128).
    const float4* src = seq + (size_t)(b * KT + t0) * NQ;
    float4 tmax = make_float4(-CUDART_INF_F, -CUDART_INF_F,
                              -CUDART_INF_F, -CUDART_INF_F);
    const int nstage = nrows * NQ;
    #pragma unroll 4
    for (int i = tid; i < nstage; i += NTHREADS) {
        float4 v = __ldg(&src[i]);
        sm[i] = v;
        tmax = f4max(tmax, v);
    }
    __syncthreads();

    const float Lf = (float)L;

    // ---- Per-window clipped passes. Fully unrolled => ndiv/idx are constants.
    #pragma unroll
    for (int w = 0; w < KW; w++) {
        const int ndiv = (w == 0) ? 1 : ((w < 5) ? 4 : 16);
        const int idx  = (w == 0) ? 0 : ((w < 5) ? (w - 1) : (w - 5));

        // Exact replication of reference f32 math (fast-math proof):
        //   div_len = ceil(L/ndiv - 1e-8)   (L/4, L/16 via exact mul by 0.25/0.0625)
        //   start   = rint((L - div_len)/(ndiv-1) * idx)   (round half to even)
        const float dlf = ceilf(__fmul_rn(Lf, 1.0f / (float)ndiv) - 1e-8f);
        const int dl = (int)dlf;
        int s = 0;
        if (ndiv > 1) {
            s = (int)rintf(__fmul_rn(__fdiv_rn(Lf - dlf, (float)(ndiv - 1)),
                                     (float)idx));
        }
        const int e  = s + dl;
        const int a  = max(s, t0);
        const int bb = min(e, t1);
        if (a >= bb) continue;   // uniform across CTA — no divergence

        float4 acc;
        if (a == t0 && bb == t1) {
            // Window fully contains this tile slab: reuse staged column max.
            acc = tmax;
        } else {
            acc = make_float4(-CUDART_INF_F, -CUDART_INF_F,
                              -CUDART_INF_F, -CUDART_INF_F);
            const int r0 = a - t0, r1 = bb - t0;
            #pragma unroll 4
            for (int r = r0; r < r1; r++) {
                acc = f4max(acc, sm[r * NQ + tid]);
            }
        }

        float* o = out + (size_t)(b * KW + w) * KC + tid * 4;
        atomic_max_f32(o + 0, acc.x);
        atomic_max_f32(o + 1, acc.y);
        atomic_max_f32(o + 2, acc.z);
        atomic_max_f32(o + 3, acc.w);
    }
}

extern "C" void kernel_launch(void* const* d_in, const int* in_sizes, int n_in,
                              void* d_out, int out_size) {
    const float4* seq     = (const float4*)d_in[0];
    const int*    lengths = (const int*)d_in[1];
    float*        out     = (float*)d_out;

    // Initialize output to -inf (harness poisons it to 0xAA before timing).
    spp_init_kernel<<<(out_size + 255) / 256, 256>>>(out, out_size);

    dim3 grid(KT / TILE, KB);
    spp_kernel<<<grid, NTHREADS>>>(seq, lengths, out);
}

// round 3
// speedup vs baseline: 1.0977x; 1.0977x over previous
#include <cuda_runtime.h>
#include <math_constants.h>

// Problem constants (fixed shapes from reference)
#define KB 32          // batch
#define KT 8192        // time
#define KC 256         // channels
#define KW 21          // windows: 1 + 4 + 16
#define TILE 32        // rows staged per CTA
#define NQ  64         // float4 quads per row (KC/4)
#define NTHREADS 256   // 4 row-groups x 64 quads
#define NRG 4          // row groups (NTHREADS / NQ)

__device__ __forceinline__ void atomic_max_f32(float* addr, float v) {
    // Order-isomorphic int trick; correct for all non-NaN floats.
    if (v >= 0.0f) {
        atomicMax(reinterpret_cast<int*>(addr), __float_as_int(v));
    } else {
        atomicMin(reinterpret_cast<unsigned int*>(addr), __float_as_uint(v));
    }
}

__global__ void spp_init_kernel(float* __restrict__ out, int n) {
    int i = blockIdx.x * blockDim.x + threadIdx.x;
    if (i < n) out[i] = -CUDART_INF_F;
}

__device__ __forceinline__ float4 f4max(float4 a, float4 b) {
    a.x = fmaxf(a.x, b.x);
    a.y = fmaxf(a.y, b.y);
    a.z = fmaxf(a.z, b.z);
    a.w = fmaxf(a.w, b.w);
    return a;
}

__global__ __launch_bounds__(NTHREADS) void spp_kernel(
    const float4* __restrict__ seq,     // [B, T, C] as float4: [B, T, NQ]
    const int* __restrict__ lengths,    // [B]
    float* __restrict__ out)            // [B, W, C]
{
    __shared__ float4 sm[TILE * NQ];        // 32 KB staged tile
    __shared__ float4 red[NRG * NQ];        // 4 KB cross-row-group reduce

    const int b  = blockIdx.y;
    const int L  = lengths[b];
    const int t0 = blockIdx.x * TILE;
    if (t0 >= L) return;

    const int nrows = min(TILE, L - t0);
    const int t1    = t0 + nrows;
    const int tid   = threadIdx.x;
    const int quad  = tid & (NQ - 1);       // channel quad, 0..63
    const int rg    = tid >> 6;             // row group, 0..3

    // ---- Stage tile into SMEM, computing per-thread partial column max.
    // i = tid + k*256  =>  i%64 == quad (coalesced 128-bit, conflict-free),
    // row(i) = rg + 4k  => this thread covers rows ≡ rg (mod 4).
    const float4* src = seq + (size_t)(b * KT + t0) * NQ;
    float4 tmax = make_float4(-CUDART_INF_F, -CUDART_INF_F,
                              -CUDART_INF_F, -CUDART_INF_F);
    const int nstage = nrows * NQ;
    #pragma unroll 8
    for (int i = tid; i < nstage; i += NTHREADS) {
        float4 v = __ldg(&src[i]);
        sm[i] = v;
        tmax = f4max(tmax, v);
    }
    __syncthreads();

    const float Lf = (float)L;

    // ---- Per-window clipped passes. Fully unrolled => ndiv/idx constants.
    #pragma unroll
    for (int w = 0; w < KW; w++) {
        const int ndiv = (w == 0) ? 1 : ((w < 5) ? 4 : 16);
        const int idx  = (w == 0) ? 0 : ((w < 5) ? (w - 1) : (w - 5));

        // Exact replication of reference f32 math (fast-math proof):
        //   div_len = ceil(L/ndiv - 1e-8)
        //   start   = rint((L - div_len)/(ndiv-1) * idx)   (round half even)
        const float dlf = ceilf(__fmul_rn(Lf, 1.0f / (float)ndiv) - 1e-8f);
        int s = 0;
        if (ndiv > 1) {
            s = (int)rintf(__fmul_rn(__fdiv_rn(Lf - dlf, (float)(ndiv - 1)),
                                     (float)idx));
        }
        const int e  = s + (int)dlf;
        const int a  = max(s, t0);
        const int bb = min(e, t1);
        if (a >= bb) continue;   // uniform across CTA — no divergence

        float4 acc;
        if (a == t0 && bb == t1) {
            // Window fully contains this tile slab: reuse staged partial max.
            acc = tmax;
        } else {
            acc = make_float4(-CUDART_INF_F, -CUDART_INF_F,
                              -CUDART_INF_F, -CUDART_INF_F);
            const int r0 = a - t0, r1 = bb - t0;
            // Rows ≡ rg (mod 4) within [r0, r1); union over rg covers all.
            int r = r0 + ((rg - r0) & (NRG - 1));
            for (; r < r1; r += NRG) {
                acc = f4max(acc, sm[r * NQ + quad]);
            }
        }

        // Cross-row-group reduce in SMEM, then row-group 0 issues atomics.
        red[rg * NQ + quad] = acc;
        __syncthreads();
        if (rg == 0) {
            acc = f4max(f4max(red[quad],          red[NQ + quad]),
                        f4max(red[2 * NQ + quad], red[3 * NQ + quad]));
            float* o = out + (size_t)(b * KW + w) * KC + quad * 4;
            atomic_max_f32(o + 0, acc.x);
            atomic_max_f32(o + 1, acc.y);
            atomic_max_f32(o + 2, acc.z);
            atomic_max_f32(o + 3, acc.w);
        }
        __syncthreads();   // protect red[] before next window reuses it
    }
}

extern "C" void kernel_launch(void* const* d_in, const int* in_sizes, int n_in,
                              void* d_out, int out_size) {
    const float4* seq     = (const float4*)d_in[0];
    const int*    lengths = (const int*)d_in[1];
    float*        out     = (float*)d_out;

    // Initialize output to -inf (harness poisons it to 0xAA before timing).
    spp_init_kernel<<<(out_size + 255) / 256, 256>>>(out, out_size);

    dim3 grid(KT / TILE, KB);
    spp_kernel<<<grid, NTHREADS>>>(seq, lengths, out);
}

// round 4
// speedup vs baseline: 1.2186x; 1.1101x over previous
#include <cuda_runtime.h>
#include <math_constants.h>

// Problem constants (fixed shapes from reference)
#define KB 32          // batch
#define KT 8192        // time
#define KC 256         // channels
#define KW 21          // windows: 1 + 4 + 16
#define TILE 32        // rows per CTA
#define NQ  64         // float4 quads per row (KC/4)
#define NTHREADS 64    // 1 thread = 1 quad; every thread sees every row
#define SENT 0x7fffffff

__device__ __forceinline__ void atomic_max_f32(float* addr, float v) {
    // Order-isomorphic int trick; correct for all non-NaN floats.
    // Note: flushing -inf is a harmless no-op under this scheme.
    if (v >= 0.0f) {
        atomicMax(reinterpret_cast<int*>(addr), __float_as_int(v));
    } else {
        atomicMin(reinterpret_cast<unsigned int*>(addr), __float_as_uint(v));
    }
}

__global__ void spp_init_kernel(float* __restrict__ out, int n) {
    int i = blockIdx.x * blockDim.x + threadIdx.x;
    if (i < n) out[i] = -CUDART_INF_F;
}

__device__ __forceinline__ float4 f4max(float4 a, float4 b) {
    a.x = fmaxf(a.x, b.x);
    a.y = fmaxf(a.y, b.y);
    a.z = fmaxf(a.z, b.z);
    a.w = fmaxf(a.w, b.w);
    return a;
}
__device__ __forceinline__ float4 f4ninf() {
    return make_float4(-CUDART_INF_F, -CUDART_INF_F, -CUDART_INF_F, -CUDART_INF_F);
}

// Per-level window state machine (lives in registers; all fields warp-uniform
// except acc). Window i of this level: [rint(stepf*i), rint(stepf*i)+dl).
struct Win {
    int n;        // ndiv
    int dl;       // window length
    float stepf;  // (L - dl)/(n-1) in f32, matching reference exactly
    int i, s, e;  // current window index + bounds (SENT,SENT when exhausted)
    float4 acc;
};

__device__ __forceinline__ int win_start(const Win& w, int i) {
    // Exact replication of reference: round((L-dl)/(n-1) * i), f32, half-even.
    return (int)rintf(__fmul_rn(w.stepf, (float)i));
}

__device__ __forceinline__ void win_flush(const Win& w, float* out_lvl, int quad) {
    float* o = out_lvl + w.i * KC + quad * 4;
    atomic_max_f32(o + 0, w.acc.x);
    atomic_max_f32(o + 1, w.acc.y);
    atomic_max_f32(o + 2, w.acc.z);
    atomic_max_f32(o + 3, w.acc.w);
}

__device__ __forceinline__ void win_init(Win& w, int n, float Lf, int t0) {
    w.n = n;
    // div_len = ceil(L/n - 1e-8); 1/n mul is exact (n = 4, 16).
    float dlf = ceilf(__fmul_rn(Lf, 1.0f / (float)n) - 1e-8f);
    w.dl = (int)dlf;
    w.stepf = __fdiv_rn(Lf - dlf, (float)(n - 1));
    // Smallest i with end_i > t0 (estimate + exact fixup; loops are short).
    int i = 0;
    if (w.stepf > 0.0f) {
        i = (int)floorf(__fdiv_rn((float)(t0 - w.dl), w.stepf)) + 1;
        i = max(0, min(i, n - 1));
    }
    while (i > 0 && win_start(w, i - 1) + w.dl > t0) i--;
    while (i < n - 1 && win_start(w, i) + w.dl <= t0) i++;
    w.i = i;
    w.s = win_start(w, i);
    w.e = w.s + w.dl;
    if (w.e <= t0) { w.s = SENT; w.e = SENT; }   // defensive; ~never for live tiles
    w.acc = f4ninf();
}

// Called when all rows < t are processed and t >= w.e: flush current window,
// advance to the next window still live at row t. Back-fills already-passed
// rows of the new window from L1 (they were just streamed). Handles
// overlapping / identical windows exactly.
__device__ __forceinline__ void win_advance(Win& w, int t, int t0,
                                            const float4* __restrict__ srcq,
                                            float* out_lvl, int quad) {
    win_flush(w, out_lvl, quad);
    for (;;) {
        if (w.i >= w.n - 1) { w.s = SENT; w.e = SENT; w.acc = f4ninf(); return; }
        w.i++;
        int ns = win_start(w, w.i);
        int ne = ns + w.dl;
        float4 a = f4ninf();
        int rb = max(ns, t0), re = min(ne, t);
        for (int r = rb; r < re; r++)
            a = f4max(a, __ldg(&srcq[r * NQ]));       // L1 hits
        w.acc = a; w.s = ns; w.e = ne;
        if (ne > t) return;          // this window is current again
        win_flush(w, out_lvl, quad); // window entirely behind t (tiny-L case)
    }
}

// End-of-tile drain: flush current window, then any later windows that start
// before t1 (their rows in this tile were already streamed -> L1 back-fill).
__device__ __forceinline__ void win_drain(Win& w, int t0, int t1,
                                          const float4* __restrict__ srcq,
                                          float* out_lvl, int quad) {
    if (w.e == SENT) return;
    win_flush(w, out_lvl, quad);
    while (w.i < w.n - 1) {
        w.i++;
        int ns = win_start(w, w.i);
        if (ns >= t1) break;
        int re = min(ns + w.dl, t1);
        float4 a = f4ninf();
        for (int r = max(ns, t0); r < re; r++)
            a = f4max(a, __ldg(&srcq[r * NQ]));
        w.acc = a;
        win_flush(w, out_lvl, quad);
    }
}

__global__ __launch_bounds__(NTHREADS) void spp_kernel(
    const float4* __restrict__ seq,     // [B, T, NQ]
    const int* __restrict__ lengths,    // [B]
    float* __restrict__ out)            // [B, W, C]
{
    const int b  = blockIdx.y;
    const int L  = __ldg(&lengths[b]);
    const int t0 = blockIdx.x * TILE;
    if (t0 >= L) return;
    const int t1   = min(t0 + TILE, L);
    const int quad = threadIdx.x;

    const float4* srcq = seq + (size_t)b * KT * NQ + quad;  // row r -> srcq[r*NQ]
    const float Lf = (float)L;

    float* out_b  = out + (size_t)b * KW * KC;
    float* out_l1 = out_b + 1 * KC;   // windows 1..4
    float* out_l2 = out_b + 5 * KC;   // windows 5..20

    Win w1, w2;
    win_init(w1, 4,  Lf, t0);
    win_init(w2, 16, Lf, t0);

    float4 acc0 = f4ninf();           // level-0 window [0, L) always covers tile

    // Segmented single streaming pass: inside a segment, window membership is
    // constant -> branchless predicated inner loop; transitions at segment ends.
    int t = t0;
    while (t < t1) {
        int seg = t1;
        if (w1.e < seg) seg = w1.e;
        if (w1.s > t)   seg = min(seg, w1.s);
        if (w2.e < seg) seg = w2.e;
        if (w2.s > t)   seg = min(seg, w2.s);

        const bool in1 = (t >= w1.s);
        const bool in2 = (t >= w2.s);
        float4 a0 = acc0, a1 = w1.acc, a2 = w2.acc;
        #pragma unroll 4
        for (int r = t; r < seg; r++) {
            float4 v = __ldg(&srcq[r * NQ]);
            a0 = f4max(a0, v);
            if (in1) a1 = f4max(a1, v);
            if (in2) a2 = f4max(a2, v);
        }
        acc0 = a0; w1.acc = a1; w2.acc = a2;

        t = seg;
        if (t >= w1.e) win_advance(w1, t, t0, srcq, out_l1, quad);
        if (t >= w2.e) win_advance(w2, t, t0, srcq, out_l2, quad);
    }

    win_drain(w1, t0, t1, srcq, out_l1, quad);
    win_drain(w2, t0, t1, srcq, out_l2, quad);

    // Level-0 flush (window 0).
    float* o0 = out_b + quad * 4;
    atomic_max_f32(o0 + 0, acc0.x);
    atomic_max_f32(o0 + 1, acc0.y);
    atomic_max_f32(o0 + 2, acc0.z);
    atomic_max_f32(o0 + 3, acc0.w);
}

extern "C" void kernel_launch(void* const* d_in, const int* in_sizes, int n_in,
                              void* d_out, int out_size) {
    const float4* seq     = (const float4*)d_in[0];
    const int*    lengths = (const int*)d_in[1];
    float*        out     = (float*)d_out;

    // Initialize output to -inf (harness poisons it to 0xAA before timing).
    spp_init_kernel<<<(out_size + 255) / 256, 256>>>(out, out_size);

    dim3 grid(KT / TILE, KB);
    spp_kernel<<<grid, NTHREADS>>>(seq, lengths, out);
}